// round 2
// baseline (speedup 1.0000x reference)
#include <cuda_runtime.h>
#include <cstdint>

#define N_NODES 100000
#define N_EDGES 3200000

// Scratch (static device globals — no allocation allowed)
__device__ float g_numer[N_NODES];
__device__ float g_denom[N_NODES];

__global__ void init_kernel() {
    int i = blockIdx.x * blockDim.x + threadIdx.x;
    if (i < N_NODES) {
        g_numer[i] = 0.0f;
        g_denom[i] = 0.0f;
    }
}

// One pass over edges:
//  - pair_pred = leaky_relu([x_src, x_dst] @ Wn + ea @ We, 0.2)
//  - ex = exp(p0 - p1)          (no max-subtraction: softmax is shift-invariant)
//  - write pair_pred, write ex into attn slot
//  - denom[dst] += ex ; numer[dst] += ex * (x[src]*W00)
__global__ void edge_kernel(const float* __restrict__ x,
                            const int*   __restrict__ ei,
                            const float* __restrict__ ea,
                            const float* __restrict__ W,
                            const float* __restrict__ Wn,
                            const float* __restrict__ We,
                            float* __restrict__ attn_ex,
                            float* __restrict__ pp_out)
{
    __shared__ float sWe[32];
    __shared__ float sWn[4];
    __shared__ float sW0;
    int t = threadIdx.x;
    if (t < 32)       sWe[t]      = We[t];
    else if (t < 36)  sWn[t - 32] = Wn[t - 32];
    else if (t == 36) sW0         = W[0];
    __syncthreads();

    int e = blockIdx.x * blockDim.x + t;
    if (e >= N_EDGES) return;

    int src = ei[e];
    int dst = ei[N_EDGES + e];
    float xs = __ldg(x + src);
    float xd = __ldg(x + dst);

    // node attention part: [xs, xd] @ Wn (Wn row-major [2,2])
    float p0 = xs * sWn[0] + xd * sWn[2];
    float p1 = xs * sWn[1] + xd * sWn[3];

    // edge (eigenvector) attention part: ea[e] @ We (We row-major [16,2])
    const float4* ea4 = (const float4*)(ea + (size_t)e * 16);
#pragma unroll
    for (int i = 0; i < 4; i++) {
        float4 v = ea4[i];
        p0 += v.x * sWe[(i * 4 + 0) * 2] + v.y * sWe[(i * 4 + 1) * 2]
            + v.z * sWe[(i * 4 + 2) * 2] + v.w * sWe[(i * 4 + 3) * 2];
        p1 += v.x * sWe[(i * 4 + 0) * 2 + 1] + v.y * sWe[(i * 4 + 1) * 2 + 1]
            + v.z * sWe[(i * 4 + 2) * 2 + 1] + v.w * sWe[(i * 4 + 3) * 2 + 1];
    }

    // leaky_relu(., 0.2)
    p0 = (p0 > 0.0f) ? p0 : 0.2f * p0;
    p1 = (p1 > 0.0f) ? p1 : 0.2f * p1;

    ((float2*)pp_out)[e] = make_float2(p0, p1);

    float ex = __expf(p0 - p1);
    attn_ex[e] = ex;

    atomicAdd(&g_denom[dst], ex);
    atomicAdd(&g_numer[dst], ex * xs * sW0);
}

__global__ void node_kernel(float* __restrict__ out) {
    int i = blockIdx.x * blockDim.x + threadIdx.x;
    if (i < N_NODES) {
        out[i] = g_numer[i] / (g_denom[i] + 1e-16f);
    }
}

__global__ void attn_kernel(const int* __restrict__ ei,
                            float* __restrict__ attn)
{
    int e = blockIdx.x * blockDim.x + threadIdx.x;
    if (e < N_EDGES) {
        int dst = ei[N_EDGES + e];
        attn[e] = attn[e] / (g_denom[dst] + 1e-16f);
    }
}

extern "C" void kernel_launch(void* const* d_in, const int* in_sizes, int n_in,
                              void* d_out, int out_size)
{
    // Resolve inputs by element count (all distinct) — robust to ordering.
    const float* x  = nullptr;   // 100000
    const int*   ei = nullptr;   // 6400000 (int32: JAX x64 disabled downcasts int64)
    const float* ea = nullptr;   // 51200000
    const float* W  = nullptr;   // 1
    const float* Wn = nullptr;   // 4
    const float* We = nullptr;   // 32
    for (int i = 0; i < n_in; i++) {
        switch (in_sizes[i]) {
            case N_NODES:      x  = (const float*)d_in[i]; break;
            case 2 * N_EDGES:  ei = (const int*)d_in[i];   break;
            case 16 * N_EDGES: ea = (const float*)d_in[i]; break;
            case 1:            W  = (const float*)d_in[i]; break;
            case 4:            Wn = (const float*)d_in[i]; break;
            case 32:           We = (const float*)d_in[i]; break;
        }
    }

    float* out  = (float*)d_out;                 // [N]
    float* attn = out + N_NODES;                 // [E]
    float* pp   = out + N_NODES + N_EDGES;       // [E,2]

    init_kernel<<<(N_NODES + 255) / 256, 256>>>();
    edge_kernel<<<(N_EDGES + 255) / 256, 256>>>(x, ei, ea, W, Wn, We, attn, pp);
    node_kernel<<<(N_NODES + 255) / 256, 256>>>(out);
    attn_kernel<<<(N_EDGES + 255) / 256, 256>>>(ei, attn);
}